// round 3
// baseline (speedup 1.0000x reference)
#include <cuda_runtime.h>
#include <cstddef>

#define BATCH 8
#define HW 512
#define NLEV 9

// Pyramid scratch for levels 1..8, NHWC (C=2) per level, batch-major.
// sizes (floats): l1:1048576 l2:262144 l3:65536 l4:16384 l5:4096 l6:1024 l7:256 l8:64
__device__ __align__(16) float g_pyr[1398080];

// float offsets of level l (l=1..8) inside g_pyr; index 0 unused.
__constant__ int c_off[9] = {0, 0, 1048576, 1310720, 1376256, 1392640, 1396736, 1397760, 1398016};

// 2x2 average pool: level lsrc -> level lsrc+1. Both channels per thread.
__global__ void pool_kernel(const float* __restrict__ x, int lsrc) {
    const int Ss = HW >> lsrc;        // source spatial size
    const int Sd = Ss >> 1;           // dest spatial size
    const int n = BATCH * Sd * Sd;
    int i = blockIdx.x * blockDim.x + threadIdx.x;
    if (i >= n) return;
    int wd = i % Sd;
    int t  = i / Sd;
    int hd = t % Sd;
    int b  = t / Sd;

    const float* src = (lsrc == 0) ? x : (g_pyr + c_off[lsrc]);
    float*       dst = g_pyr + c_off[lsrc + 1];

    size_t s0 = ((size_t)(b * Ss + 2 * hd) * Ss + 2 * wd) * 2;      // multiple of 4 (Ss even)
    size_t s1 = s0 + (size_t)Ss * 2;
    float4 a = *(const float4*)(src + s0);   // px(2w),px(2w+1) ch-interleaved
    float4 c = *(const float4*)(src + s1);
    float2 o;
    o.x = (a.x + a.z + c.x + c.z) * 0.25f;
    o.y = (a.y + a.w + c.y + c.w) * 0.25f;
    *(float2*)(dst + ((size_t)(b * Sd + hd) * Sd + wd) * 2) = o;
}

// Upsample every level back to 512x512 with JAX half-pixel bilinear and write
// the transposed output: out[b, l*2+c, h, w]. One thread = 4 w-pixels x 2 ch.
__global__ void up_kernel(const float* __restrict__ x, float* __restrict__ out) {
    const int bl = blockIdx.z;
    const int b = bl / NLEV;
    const int l = bl % NLEV;
    const int h = blockIdx.y;
    const int w = (blockIdx.x * blockDim.x + threadIdx.x) * 4;   // 0..508
    if (w >= HW) return;

    float* out0 = out + (((size_t)(b * 2 * NLEV + l * 2) * HW + h) * HW + w);
    float* out1 = out0 + (size_t)HW * HW;

    if (l == 0) {
        // identity resize: transposed copy of input channels
        const float2* src = (const float2*)(x) + ((size_t)(b * HW + h) * HW + w);
        float2 p0 = src[0], p1 = src[1], p2 = src[2], p3 = src[3];
        *(float4*)out0 = make_float4(p0.x, p1.x, p2.x, p3.x);
        *(float4*)out1 = make_float4(p0.y, p1.y, p2.y, p3.y);
        return;
    }

    const int   S   = HW >> l;
    const float inv = 1.0f / (float)(1 << l);
    const float2* src = (const float2*)(g_pyr + c_off[l]) + (size_t)b * S * S;

    float sfh = (h + 0.5f) * inv - 0.5f;
    int   ifh = (int)floorf(sfh);
    float fh  = sfh - (float)ifh;
    int ih0 = ifh < 0 ? 0 : (ifh > S - 1 ? S - 1 : ifh);
    int ih1 = (ifh + 1) < 0 ? 0 : ((ifh + 1) > S - 1 ? S - 1 : ifh + 1);
    const float2* r0 = src + (size_t)ih0 * S;
    const float2* r1 = src + (size_t)ih1 * S;
    const float wy0 = 1.0f - fh;

    float4 o0, o1;
    float* po0 = &o0.x;
    float* po1 = &o1.x;
#pragma unroll
    for (int k = 0; k < 4; ++k) {
        float sfw = (w + k + 0.5f) * inv - 0.5f;
        int   ifw = (int)floorf(sfw);
        float fw  = sfw - (float)ifw;
        int iw0 = ifw < 0 ? 0 : (ifw > S - 1 ? S - 1 : ifw);
        int iw1 = (ifw + 1) < 0 ? 0 : ((ifw + 1) > S - 1 ? S - 1 : ifw + 1);
        float2 v00 = r0[iw0], v01 = r0[iw1];
        float2 v10 = r1[iw0], v11 = r1[iw1];
        float wx0 = 1.0f - fw;
        float tx = v00.x * wx0 + v01.x * fw;
        float bx = v10.x * wx0 + v11.x * fw;
        float ty = v00.y * wx0 + v01.y * fw;
        float by = v10.y * wx0 + v11.y * fw;
        po0[k] = tx * wy0 + bx * fh;
        po1[k] = ty * wy0 + by * fh;
    }
    *(float4*)out0 = o0;
    *(float4*)out1 = o1;
}

extern "C" void kernel_launch(void* const* d_in, const int* in_sizes, int n_in,
                              void* d_out, int out_size) {
    const float* x = (const float*)d_in[0];
    float* out = (float*)d_out;

    // Build pyramid: levels 1..8
    for (int lsrc = 0; lsrc < NLEV - 1; ++lsrc) {
        int Sd = (HW >> lsrc) >> 1;
        int n = BATCH * Sd * Sd;
        int blocks = (n + 255) / 256;
        pool_kernel<<<blocks, 256>>>(x, lsrc);
    }

    // Upsample all levels + write transposed output
    dim3 grid(1, HW, BATCH * NLEV);   // (w-chunks, h, b*l)
    up_kernel<<<grid, 128>>>(x, out);
}

// round 5
// speedup vs baseline: 1.1232x; 1.1232x over previous
#include <cuda_runtime.h>
#include <cstddef>

#define BATCH 8
#define HW 512
#define NLEV 9

// Pyramid scratch for levels 1..8, NHWC (C=2) per level, batch-major.
__device__ __align__(16) float g_pyr[1398080];

// float offsets of level l (l=1..8) inside g_pyr; index 0 unused.
__constant__ int c_off[9] = {0, 0, 1048576, 1310720, 1376256, 1392640, 1396736, 1397760, 1398016};

// Big pool: level 0 (input, 512x512) -> level 1 (256x256). Bandwidth-bound.
__global__ void pool1_kernel(const float* __restrict__ x) {
    const int Ss = HW, Sd = HW / 2;
    const int n = BATCH * Sd * Sd;
    int i = blockIdx.x * blockDim.x + threadIdx.x;
    if (i >= n) return;
    int wd = i % Sd;
    int t  = i / Sd;
    int hd = t % Sd;
    int b  = t / Sd;

    size_t s0 = ((size_t)(b * Ss + 2 * hd) * Ss + 2 * wd) * 2;
    size_t s1 = s0 + (size_t)Ss * 2;
    float4 a = *(const float4*)(x + s0);
    float4 c = *(const float4*)(x + s1);
    float2 o;
    o.x = (a.x + a.z + c.x + c.z) * 0.25f;
    o.y = (a.y + a.w + c.y + c.w) * 0.25f;
    *(float2*)(g_pyr + c_off[1] + ((size_t)(b * Sd + hd) * Sd + wd) * 2) = o;
}

// Fused pools: levels 1->2->...->8, one block per batch image.
// All data is L2-resident (<=4.2MB); within-block gmem write->__syncthreads->read
// is coherent, so we chain levels through gmem with no extra launches.
__global__ void pool_rest_kernel() {
    const int b = blockIdx.x;
#pragma unroll
    for (int l = 1; l <= NLEV - 2; ++l) {
        const int Ss = HW >> l;
        const int Sd = Ss >> 1;
        const float* src = g_pyr + c_off[l]     + (size_t)b * Ss * Ss * 2;
        float*       dst = g_pyr + c_off[l + 1] + (size_t)b * Sd * Sd * 2;
        const int n = Sd * Sd;
        for (int i = threadIdx.x; i < n; i += blockDim.x) {
            int wd = i % Sd;
            int hd = i / Sd;
            float4 a = *(const float4*)(src + ((size_t)(2 * hd) * Ss + 2 * wd) * 2);
            float4 c = *(const float4*)(src + ((size_t)(2 * hd + 1) * Ss + 2 * wd) * 2);
            float2 o;
            o.x = (a.x + a.z + c.x + c.z) * 0.25f;
            o.y = (a.y + a.w + c.y + c.w) * 0.25f;
            *(float2*)(dst + ((size_t)hd * Sd + wd) * 2) = o;
        }
        __syncthreads();
    }
}

// Upsample every level back to 512x512 with JAX half-pixel bilinear and write
// the transposed output: out[b, l*2+c, h, w]. One thread = 4 w-pixels x 2 ch.
__global__ void up_kernel(const float* __restrict__ x, float* __restrict__ out) {
    const int bl = blockIdx.z;
    const int b = bl / NLEV;
    const int l = bl % NLEV;
    const int h = blockIdx.y;
    const int w = (blockIdx.x * blockDim.x + threadIdx.x) * 4;   // 0..508
    if (w >= HW) return;

    float* out0 = out + (((size_t)(b * 2 * NLEV + l * 2) * HW + h) * HW + w);
    float* out1 = out0 + (size_t)HW * HW;

    if (l == 0) {
        // identity resize: transposed copy of input channels (vectorized)
        const float4* src = (const float4*)(x + ((size_t)(b * HW + h) * HW + w) * 2);
        float4 q0 = src[0];   // px w, w+1 interleaved
        float4 q1 = src[1];   // px w+2, w+3
        *(float4*)out0 = make_float4(q0.x, q0.z, q1.x, q1.z);
        *(float4*)out1 = make_float4(q0.y, q0.w, q1.y, q1.w);
        return;
    }

    const int   S   = HW >> l;
    const float inv = 1.0f / (float)(1 << l);
    const float2* src = (const float2*)(g_pyr + c_off[l]) + (size_t)b * S * S;

    float sfh = (h + 0.5f) * inv - 0.5f;
    int   ifh = (int)floorf(sfh);
    float fh  = sfh - (float)ifh;
    int ih0 = ifh < 0 ? 0 : (ifh > S - 1 ? S - 1 : ifh);
    int ih1 = (ifh + 1) < 0 ? 0 : ((ifh + 1) > S - 1 ? S - 1 : ifh + 1);
    const float2* r0 = src + (size_t)ih0 * S;
    const float2* r1 = src + (size_t)ih1 * S;
    const float wy0 = 1.0f - fh;

    float4 o0, o1;
    float* po0 = &o0.x;
    float* po1 = &o1.x;
#pragma unroll
    for (int k = 0; k < 4; ++k) {
        float sfw = (w + k + 0.5f) * inv - 0.5f;
        int   ifw = (int)floorf(sfw);
        float fw  = sfw - (float)ifw;
        int iw0 = ifw < 0 ? 0 : (ifw > S - 1 ? S - 1 : ifw);
        int iw1 = (ifw + 1) < 0 ? 0 : ((ifw + 1) > S - 1 ? S - 1 : ifw + 1);
        float2 v00 = r0[iw0], v01 = r0[iw1];
        float2 v10 = r1[iw0], v11 = r1[iw1];
        float wx0 = 1.0f - fw;
        float tx = v00.x * wx0 + v01.x * fw;
        float bx = v10.x * wx0 + v11.x * fw;
        float ty = v00.y * wx0 + v01.y * fw;
        float by = v10.y * wx0 + v11.y * fw;
        po0[k] = tx * wy0 + bx * fh;
        po1[k] = ty * wy0 + by * fh;
    }
    *(float4*)out0 = o0;
    *(float4*)out1 = o1;
}

extern "C" void kernel_launch(void* const* d_in, const int* in_sizes, int n_in,
                              void* d_out, int out_size) {
    const float* x = (const float*)d_in[0];
    float* out = (float*)d_out;

    // Level 0 -> 1: bandwidth-bound, full grid.
    {
        int n = BATCH * (HW / 2) * (HW / 2);
        pool1_kernel<<<(n + 255) / 256, 256>>>(x);
    }

    // Levels 1 -> 8 fused in one launch (one block per batch, L2-resident).
    pool_rest_kernel<<<BATCH, 1024>>>();

    // Upsample all levels + write transposed output.
    dim3 grid(1, HW, BATCH * NLEV);   // (w-chunks, h, b*l)
    up_kernel<<<grid, 128>>>(x, out);
}

// round 7
// speedup vs baseline: 1.2092x; 1.0766x over previous
#include <cuda_runtime.h>
#include <cstddef>

#define BATCH 8
#define HW 512
#define NLEV 9

// Pyramid scratch for levels 1..6 (7,8 are computed on the fly), NHWC (C=2).
__device__ __align__(16) float g_pyr[1398080];

// float offsets of level l (l=1..8) inside g_pyr; index 0 unused.
__constant__ int c_off[9] = {0, 0, 1048576, 1310720, 1376256, 1392640, 1396736, 1397760, 1398016};

// ---------------------------------------------------------------------------
// pool1: input (512) -> level 1 (256). 4 dest px per thread, MLP=8.
__global__ void pool1_kernel(const float* __restrict__ x) {
    const int Ss = HW, Sd = HW / 2;
    const int n = BATCH * Sd * (Sd / 4);
    int i = blockIdx.x * blockDim.x + threadIdx.x;
    if (i >= n) return;
    int wq = i % (Sd / 4);            // dest w block of 4
    int t  = i / (Sd / 4);
    int hd = t % Sd;
    int b  = t / Sd;
    int wd = wq * 4;

    const float4* r0 = (const float4*)(x + ((size_t)(b * Ss + 2 * hd) * Ss + 2 * wd) * 2);
    const float4* r1 = (const float4*)((const float*)r0 + (size_t)Ss * 2);
    float4 a0 = r0[0], a1 = r0[1], a2 = r0[2], a3 = r0[3];
    float4 c0 = r1[0], c1 = r1[1], c2 = r1[2], c3 = r1[3];
    float4 o0, o1;
    o0.x = (a0.x + a0.z + c0.x + c0.z) * 0.25f;
    o0.y = (a0.y + a0.w + c0.y + c0.w) * 0.25f;
    o0.z = (a1.x + a1.z + c1.x + c1.z) * 0.25f;
    o0.w = (a1.y + a1.w + c1.y + c1.w) * 0.25f;
    o1.x = (a2.x + a2.z + c2.x + c2.z) * 0.25f;
    o1.y = (a2.y + a2.w + c2.y + c2.w) * 0.25f;
    o1.z = (a3.x + a3.z + c3.x + c3.z) * 0.25f;
    o1.w = (a3.y + a3.w + c3.y + c3.w) * 0.25f;
    float4* dst = (float4*)(g_pyr + ((size_t)(b * Sd + hd) * Sd + wd) * 2);
    dst[0] = o0;
    dst[1] = o1;
}

// ---------------------------------------------------------------------------
// pool_rest: levels 1->2->...->6. Pooling is h-local, so h-stripes are
// dependency-clean: block (b, p) owns rows [p*Sd/8, (p+1)*Sd/8) of every dest
// level and reads only its own stripe of the src level. 64 independent blocks.
__global__ void pool_rest_kernel() {
    const int p = blockIdx.x & 7;
    const int b = blockIdx.x >> 3;
#pragma unroll
    for (int l = 1; l <= 5; ++l) {
        const int Ss = HW >> l;
        const int Sd = Ss >> 1;
        const int rows = Sd >> 3;             // dest rows per stripe (16..1)
        const float* src = g_pyr + c_off[l]     + (size_t)b * Ss * Ss * 2;
        float*       dst = g_pyr + c_off[l + 1] + (size_t)b * Sd * Sd * 2;
        const int r0 = p * rows;
        const int n = rows * Sd;
        for (int i = threadIdx.x; i < n; i += blockDim.x) {
            int wd = i % Sd;
            int hd = r0 + i / Sd;
            float4 a = *(const float4*)(src + ((size_t)(2 * hd) * Ss + 2 * wd) * 2);
            float4 c = *(const float4*)(src + ((size_t)(2 * hd + 1) * Ss + 2 * wd) * 2);
            float2 o;
            o.x = (a.x + a.z + c.x + c.z) * 0.25f;
            o.y = (a.y + a.w + c.y + c.w) * 0.25f;
            *(float2*)(dst + ((size_t)hd * Sd + wd) * 2) = o;
        }
        __syncthreads();
    }
}

// ---------------------------------------------------------------------------
// Fetch one source sample (2 channels) of level L at (ih, iw).
// L<=6: direct from g_pyr. L=7: 2x2 pool of level 6. L=8: 4x4 pool of level 6.
template <int L>
__device__ __forceinline__ float2 fetch_px(const float* __restrict__ lvlbase,
                                           int ih, int iw) {
    if constexpr (L <= 6) {
        constexpr int S = HW >> L;
        return *(const float2*)(lvlbase + ((size_t)ih * S + iw) * 2);
    } else if constexpr (L == 7) {
        // lvlbase = level 6 (8x8) for this batch
        const float4 a = *(const float4*)(lvlbase + ((size_t)(2 * ih) * 8 + 2 * iw) * 2);
        const float4 c = *(const float4*)(lvlbase + ((size_t)(2 * ih + 1) * 8 + 2 * iw) * 2);
        return make_float2((a.x + a.z + c.x + c.z) * 0.25f,
                           (a.y + a.w + c.y + c.w) * 0.25f);
    } else {
        // L == 8: 4x4 pool of level 6
        float sx = 0.f, sy = 0.f;
#pragma unroll
        for (int rr = 0; rr < 4; ++rr) {
            const float4 q0 = *(const float4*)(lvlbase + ((size_t)(4 * ih + rr) * 8 + 4 * iw) * 2);
            const float4 q1 = *(const float4*)(lvlbase + ((size_t)(4 * ih + rr) * 8 + 4 * iw + 2) * 2);
            sx += q0.x + q0.z + q1.x + q1.z;
            sy += q0.y + q0.w + q1.y + q1.w;
        }
        return make_float2(sx * 0.0625f, sy * 0.0625f);
    }
}

// ---------------------------------------------------------------------------
// up: each thread produces 8 consecutive w outputs for both channels.
template <int L>
__device__ __forceinline__ void up_body(const float* __restrict__ x,
                                        float* __restrict__ out, int b, int h) {
    const int t = threadIdx.x;            // 0..63
    const int w = t * 8;
    float* out0 = out + (((size_t)(b * 2 * NLEV + 2 * L) * HW + h) * HW + w);
    float* out1 = out0 + (size_t)HW * HW;

    if constexpr (L == 0) {
        const float4* src = (const float4*)(x + ((size_t)(b * HW + h) * HW + w) * 2);
        float4 q0 = src[0], q1 = src[1], q2 = src[2], q3 = src[3];
        ((float4*)out0)[0] = make_float4(q0.x, q0.z, q1.x, q1.z);
        ((float4*)out0)[1] = make_float4(q2.x, q2.z, q3.x, q3.z);
        ((float4*)out1)[0] = make_float4(q0.y, q0.w, q1.y, q1.w);
        ((float4*)out1)[1] = make_float4(q2.y, q2.w, q3.y, q3.w);
        return;
    } else {
        constexpr int F = 1 << L;
        constexpr int S = HW >> L;        // sampling-grid size of level L
        constexpr float INV = 1.0f / F;

        const float* lvlbase;
        if constexpr (L <= 6)
            lvlbase = g_pyr + c_off[L] + (size_t)b * S * S * 2;
        else
            lvlbase = g_pyr + c_off[6] + (size_t)b * 8 * 8 * 2;   // level 6

        // vertical
        float sfh = (h + 0.5f) * INV - 0.5f;
        int   ifh = (int)floorf(sfh);
        float fh  = sfh - (float)ifh;
        int ih0 = min(max(ifh, 0), S - 1);
        int ih1 = min(max(ifh + 1, 0), S - 1);
        const float wy0 = 1.0f - fh;

        // proper contiguous register arrays for the 8 outputs per channel
        float po0[8];
        float po1[8];

        if constexpr (L <= 3) {
            // per-k column offsets & weights are t-invariant (compile-time)
            constexpr int NC = (8 >> L) + 2;        // distinct columns needed
            constexpr int OFF1[8] = {0,1,1,2,2,3,3,4};
            constexpr int OFF2[8] = {0,0,1,1,1,1,2,2};
            constexpr int OFF3[8] = {0,0,0,0,1,1,1,1};
            constexpr float FW1[8] = {0.75f,0.25f,0.75f,0.25f,0.75f,0.25f,0.75f,0.25f};
            constexpr float FW2[8] = {0.625f,0.875f,0.125f,0.375f,0.625f,0.875f,0.125f,0.375f};
            constexpr float FW3[8] = {0.5625f,0.6875f,0.8125f,0.9375f,0.0625f,0.1875f,0.3125f,0.4375f};
            const int c0 = (w >> L) - 1;
            float2 a0[NC], a1[NC];
#pragma unroll
            for (int j = 0; j < NC; ++j) {
                int ci = min(max(c0 + j, 0), S - 1);
                a0[j] = fetch_px<L>(lvlbase, ih0, ci);
                a1[j] = fetch_px<L>(lvlbase, ih1, ci);
            }
#pragma unroll
            for (int k = 0; k < 8; ++k) {
                const int   off = (L == 1) ? OFF1[k] : (L == 2) ? OFF2[k] : OFF3[k];
                const float fw  = (L == 1) ? FW1[k]  : (L == 2) ? FW2[k]  : FW3[k];
                const float wx0 = 1.0f - fw;
                float2 v00 = a0[off], v01 = a0[off + 1];
                float2 v10 = a1[off], v11 = a1[off + 1];
                float tx = v00.x * wx0 + v01.x * fw;
                float bx = v10.x * wx0 + v11.x * fw;
                float ty = v00.y * wx0 + v01.y * fw;
                float by = v10.y * wx0 + v11.y * fw;
                po0[k] = tx * wy0 + bx * fh;
                po1[k] = ty * wy0 + by * fh;
            }
        } else {
            // L >= 4: all 8 outputs straddle at most 2 source columns
            float sfw0 = (w + 0.5f) * INV - 0.5f;
            int   c0f  = (int)floorf(sfw0);
            float2 a0[3], a1[3];
#pragma unroll
            for (int j = 0; j < 3; ++j) {
                int ci = min(max(c0f + j, 0), S - 1);
                a0[j] = fetch_px<L>(lvlbase, ih0, ci);
                a1[j] = fetch_px<L>(lvlbase, ih1, ci);
            }
#pragma unroll
            for (int k = 0; k < 8; ++k) {
                float sfw = (w + k + 0.5f) * INV - 0.5f;
                int   ifw = (int)floorf(sfw);
                float fw  = sfw - (float)ifw;
                bool  hi  = (ifw != c0f);
                float2 v00 = hi ? a0[1] : a0[0];
                float2 v01 = hi ? a0[2] : a0[1];
                float2 v10 = hi ? a1[1] : a1[0];
                float2 v11 = hi ? a1[2] : a1[1];
                const float wx0 = 1.0f - fw;
                float tx = v00.x * wx0 + v01.x * fw;
                float bx = v10.x * wx0 + v11.x * fw;
                float ty = v00.y * wx0 + v01.y * fw;
                float by = v10.y * wx0 + v11.y * fw;
                po0[k] = tx * wy0 + bx * fh;
                po1[k] = ty * wy0 + by * fh;
            }
        }
        ((float4*)out0)[0] = make_float4(po0[0], po0[1], po0[2], po0[3]);
        ((float4*)out0)[1] = make_float4(po0[4], po0[5], po0[6], po0[7]);
        ((float4*)out1)[0] = make_float4(po1[0], po1[1], po1[2], po1[3]);
        ((float4*)out1)[1] = make_float4(po1[4], po1[5], po1[6], po1[7]);
    }
}

__global__ void up_kernel(const float* __restrict__ x, float* __restrict__ out) {
    const int bl = blockIdx.z;
    const int b  = bl / NLEV;
    const int l  = bl % NLEV;
    const int h  = blockIdx.y * 2 + threadIdx.y;
    switch (l) {
        case 0: up_body<0>(x, out, b, h); break;
        case 1: up_body<1>(x, out, b, h); break;
        case 2: up_body<2>(x, out, b, h); break;
        case 3: up_body<3>(x, out, b, h); break;
        case 4: up_body<4>(x, out, b, h); break;
        case 5: up_body<5>(x, out, b, h); break;
        case 6: up_body<6>(x, out, b, h); break;
        case 7: up_body<7>(x, out, b, h); break;
        case 8: up_body<8>(x, out, b, h); break;
    }
}

extern "C" void kernel_launch(void* const* d_in, const int* in_sizes, int n_in,
                              void* d_out, int out_size) {
    const float* x = (const float*)d_in[0];
    float* out = (float*)d_out;

    // Level 0 -> 1: bandwidth-bound.
    {
        int n = BATCH * (HW / 2) * (HW / 2) / 4;
        pool1_kernel<<<(n + 255) / 256, 256>>>(x);
    }

    // Levels 1 -> 6: 64 independent h-stripe blocks.
    pool_rest_kernel<<<64, 256>>>();

    // Upsample all levels (7,8 on the fly from level 6) + transposed write.
    dim3 grid(1, HW / 2, BATCH * NLEV);
    dim3 block(64, 2);
    up_kernel<<<grid, block>>>(x, out);
}

// round 8
// speedup vs baseline: 1.2317x; 1.0186x over previous
#include <cuda_runtime.h>
#include <cstddef>

#define BATCH 8
#define HW 512
#define NLEV 9

// Pyramid scratch for levels 1..6 (7,8 computed on the fly), NHWC (C=2).
__device__ __align__(16) float g_pyr[1398080];

// float offsets of level l (l=1..8) inside g_pyr; index 0 unused.
__constant__ int c_off[9] = {0, 0, 1048576, 1310720, 1376256, 1392640, 1396736, 1397760, 1398016};

// ---------------------------------------------------------------------------
// pool1_copy: reads input once. Writes (a) level-1 pyramid (256x256) and
// (b) the level-0 transposed output planes (out channels 0,1).
// One thread = 2 dest px = 4 src px x 2 rows.
__global__ void pool1_copy_kernel(const float* __restrict__ x, float* __restrict__ out) {
    const int Sd = HW / 2;                       // 256
    const int n = BATCH * Sd * (Sd / 2);         // 262144
    int i = blockIdx.x * blockDim.x + threadIdx.x;
    if (i >= n) return;
    int wp = i % (Sd / 2);                       // dest w pair index (0..127)
    int t  = i / (Sd / 2);
    int hd = t % Sd;                             // dest row (0..255)
    int b  = t / Sd;
    int wd = wp * 2;                             // dest w (even)
    int ws = wd * 2;                             // src w start (0..508, mult of 4)
    int hs0 = 2 * hd, hs1 = 2 * hd + 1;

    const float4* r0 = (const float4*)(x + ((size_t)(b * HW + hs0) * HW + ws) * 2);
    const float4* r1 = (const float4*)((const float*)r0 + (size_t)HW * 2);
    float4 a0 = r0[0], a1 = r0[1];               // row hs0: px ws..ws+3 (ch-interleaved)
    float4 c0 = r1[0], c1 = r1[1];               // row hs1

    // level-1 pyramid (2 dest px, both channels)
    float4 p;
    p.x = (a0.x + a0.z + c0.x + c0.z) * 0.25f;
    p.y = (a0.y + a0.w + c0.y + c0.w) * 0.25f;
    p.z = (a1.x + a1.z + c1.x + c1.z) * 0.25f;
    p.w = (a1.y + a1.w + c1.y + c1.w) * 0.25f;
    *(float4*)(g_pyr + ((size_t)(b * Sd + hd) * Sd + wd) * 2) = p;

    // level-0 transposed output: out[b, ch, hs, ws..ws+3]
    float* o00 = out + (((size_t)(b * 2 * NLEV + 0) * HW + hs0) * HW + ws);
    float* o01 = o00 + (size_t)HW;               // row hs1, ch0
    float* o10 = out + (((size_t)(b * 2 * NLEV + 1) * HW + hs0) * HW + ws);
    float* o11 = o10 + (size_t)HW;
    *(float4*)o00 = make_float4(a0.x, a0.z, a1.x, a1.z);
    *(float4*)o01 = make_float4(c0.x, c0.z, c1.x, c1.z);
    *(float4*)o10 = make_float4(a0.y, a0.w, a1.y, a1.w);
    *(float4*)o11 = make_float4(c0.y, c0.w, c1.y, c1.w);
}

// ---------------------------------------------------------------------------
// pool_rest: levels 1->2->...->6. Pooling is h-local, so h-stripes are
// dependency-clean: block (b, p) owns rows [p*Sd/8, (p+1)*Sd/8) of every dest
// level and reads only its own stripe of the src level. 64 independent blocks.
__global__ void pool_rest_kernel() {
    const int p = blockIdx.x & 7;
    const int b = blockIdx.x >> 3;
#pragma unroll
    for (int l = 1; l <= 5; ++l) {
        const int Ss = HW >> l;
        const int Sd = Ss >> 1;
        const int rows = Sd >> 3;             // dest rows per stripe (16..1)
        const float* src = g_pyr + c_off[l]     + (size_t)b * Ss * Ss * 2;
        float*       dst = g_pyr + c_off[l + 1] + (size_t)b * Sd * Sd * 2;
        const int r0 = p * rows;
        const int n = rows * Sd;
        for (int i = threadIdx.x; i < n; i += blockDim.x) {
            int wd = i % Sd;
            int hd = r0 + i / Sd;
            float4 a = *(const float4*)(src + ((size_t)(2 * hd) * Ss + 2 * wd) * 2);
            float4 c = *(const float4*)(src + ((size_t)(2 * hd + 1) * Ss + 2 * wd) * 2);
            float2 o;
            o.x = (a.x + a.z + c.x + c.z) * 0.25f;
            o.y = (a.y + a.w + c.y + c.w) * 0.25f;
            *(float2*)(dst + ((size_t)hd * Sd + wd) * 2) = o;
        }
        __syncthreads();
    }
}

// ---------------------------------------------------------------------------
// Fetch one source sample (2 channels) of level L at (ih, iw).
// L<=6: direct from g_pyr. L=7: 2x2 pool of level 6. L=8: 4x4 pool of level 6.
template <int L>
__device__ __forceinline__ float2 fetch_px(const float* __restrict__ lvlbase,
                                           int ih, int iw) {
    if constexpr (L <= 6) {
        constexpr int S = HW >> L;
        return *(const float2*)(lvlbase + ((size_t)ih * S + iw) * 2);
    } else if constexpr (L == 7) {
        const float4 a = *(const float4*)(lvlbase + ((size_t)(2 * ih) * 8 + 2 * iw) * 2);
        const float4 c = *(const float4*)(lvlbase + ((size_t)(2 * ih + 1) * 8 + 2 * iw) * 2);
        return make_float2((a.x + a.z + c.x + c.z) * 0.25f,
                           (a.y + a.w + c.y + c.w) * 0.25f);
    } else {
        // L == 8: 4x4 pool of level 6
        float sx = 0.f, sy = 0.f;
#pragma unroll
        for (int rr = 0; rr < 4; ++rr) {
            const float4 q0 = *(const float4*)(lvlbase + ((size_t)(4 * ih + rr) * 8 + 4 * iw) * 2);
            const float4 q1 = *(const float4*)(lvlbase + ((size_t)(4 * ih + rr) * 8 + 4 * iw + 2) * 2);
            sx += q0.x + q0.z + q1.x + q1.z;
            sy += q0.y + q0.w + q1.y + q1.w;
        }
        return make_float2(sx * 0.0625f, sy * 0.0625f);
    }
}

// ---------------------------------------------------------------------------
// up: each thread produces 8 consecutive w outputs for both channels. L >= 1.
template <int L>
__device__ __forceinline__ void up_body(float* __restrict__ out, int b, int h) {
    const int t = threadIdx.x;            // 0..63
    const int w = t * 8;
    float* out0 = out + (((size_t)(b * 2 * NLEV + 2 * L) * HW + h) * HW + w);
    float* out1 = out0 + (size_t)HW * HW;

    constexpr int F = 1 << L;
    constexpr int S = HW >> L;
    constexpr float INV = 1.0f / F;

    const float* lvlbase;
    if constexpr (L <= 6)
        lvlbase = g_pyr + c_off[L] + (size_t)b * S * S * 2;
    else
        lvlbase = g_pyr + c_off[6] + (size_t)b * 8 * 8 * 2;   // level 6

    float sfh = (h + 0.5f) * INV - 0.5f;
    int   ifh = (int)floorf(sfh);
    float fh  = sfh - (float)ifh;
    int ih0 = min(max(ifh, 0), S - 1);
    int ih1 = min(max(ifh + 1, 0), S - 1);
    const float wy0 = 1.0f - fh;

    float po0[8];
    float po1[8];

    if constexpr (L <= 3) {
        constexpr int NC = (8 >> L) + 2;
        constexpr int OFF1[8] = {0,1,1,2,2,3,3,4};
        constexpr int OFF2[8] = {0,0,1,1,1,1,2,2};
        constexpr int OFF3[8] = {0,0,0,0,1,1,1,1};
        constexpr float FW1[8] = {0.75f,0.25f,0.75f,0.25f,0.75f,0.25f,0.75f,0.25f};
        constexpr float FW2[8] = {0.625f,0.875f,0.125f,0.375f,0.625f,0.875f,0.125f,0.375f};
        constexpr float FW3[8] = {0.5625f,0.6875f,0.8125f,0.9375f,0.0625f,0.1875f,0.3125f,0.4375f};
        const int c0 = (w >> L) - 1;
        float2 a0[NC], a1[NC];
#pragma unroll
        for (int j = 0; j < NC; ++j) {
            int ci = min(max(c0 + j, 0), S - 1);
            a0[j] = fetch_px<L>(lvlbase, ih0, ci);
            a1[j] = fetch_px<L>(lvlbase, ih1, ci);
        }
#pragma unroll
        for (int k = 0; k < 8; ++k) {
            const int   off = (L == 1) ? OFF1[k] : (L == 2) ? OFF2[k] : OFF3[k];
            const float fw  = (L == 1) ? FW1[k]  : (L == 2) ? FW2[k]  : FW3[k];
            const float wx0 = 1.0f - fw;
            float2 v00 = a0[off], v01 = a0[off + 1];
            float2 v10 = a1[off], v11 = a1[off + 1];
            float tx = v00.x * wx0 + v01.x * fw;
            float bx = v10.x * wx0 + v11.x * fw;
            float ty = v00.y * wx0 + v01.y * fw;
            float by = v10.y * wx0 + v11.y * fw;
            po0[k] = tx * wy0 + bx * fh;
            po1[k] = ty * wy0 + by * fh;
        }
    } else {
        // L >= 4: all 8 outputs straddle at most 2 source columns
        float sfw0 = (w + 0.5f) * INV - 0.5f;
        int   c0f  = (int)floorf(sfw0);
        float2 a0[3], a1[3];
#pragma unroll
        for (int j = 0; j < 3; ++j) {
            int ci = min(max(c0f + j, 0), S - 1);
            a0[j] = fetch_px<L>(lvlbase, ih0, ci);
            a1[j] = fetch_px<L>(lvlbase, ih1, ci);
        }
#pragma unroll
        for (int k = 0; k < 8; ++k) {
            float sfw = (w + k + 0.5f) * INV - 0.5f;
            int   ifw = (int)floorf(sfw);
            float fw  = sfw - (float)ifw;
            bool  hi  = (ifw != c0f);
            float2 v00 = hi ? a0[1] : a0[0];
            float2 v01 = hi ? a0[2] : a0[1];
            float2 v10 = hi ? a1[1] : a1[0];
            float2 v11 = hi ? a1[2] : a1[1];
            const float wx0 = 1.0f - fw;
            float tx = v00.x * wx0 + v01.x * fw;
            float bx = v10.x * wx0 + v11.x * fw;
            float ty = v00.y * wx0 + v01.y * fw;
            float by = v10.y * wx0 + v11.y * fw;
            po0[k] = tx * wy0 + bx * fh;
            po1[k] = ty * wy0 + by * fh;
        }
    }
    ((float4*)out0)[0] = make_float4(po0[0], po0[1], po0[2], po0[3]);
    ((float4*)out0)[1] = make_float4(po0[4], po0[5], po0[6], po0[7]);
    ((float4*)out1)[0] = make_float4(po1[0], po1[1], po1[2], po1[3]);
    ((float4*)out1)[1] = make_float4(po1[4], po1[5], po1[6], po1[7]);
}

__global__ void up_kernel(float* __restrict__ out) {
    const int bl = blockIdx.z;
    const int b  = bl >> 3;               // 8 levels per batch (l = 1..8)
    const int l  = (bl & 7) + 1;
    const int h  = blockIdx.y * 4 + threadIdx.y;
    switch (l) {
        case 1: up_body<1>(out, b, h); break;
        case 2: up_body<2>(out, b, h); break;
        case 3: up_body<3>(out, b, h); break;
        case 4: up_body<4>(out, b, h); break;
        case 5: up_body<5>(out, b, h); break;
        case 6: up_body<6>(out, b, h); break;
        case 7: up_body<7>(out, b, h); break;
        case 8: up_body<8>(out, b, h); break;
    }
}

extern "C" void kernel_launch(void* const* d_in, const int* in_sizes, int n_in,
                              void* d_out, int out_size) {
    const float* x = (const float*)d_in[0];
    float* out = (float*)d_out;

    // Input read once: level-1 pyramid + level-0 transposed output.
    {
        int n = BATCH * (HW / 2) * (HW / 4);   // 262144 threads
        pool1_copy_kernel<<<(n + 255) / 256, 256>>>(x, out);
    }

    // Levels 1 -> 6: 64 independent h-stripe blocks.
    pool_rest_kernel<<<64, 256>>>();

    // Upsample levels 1..8 (7,8 on the fly from level 6) + transposed write.
    dim3 grid(1, HW / 4, BATCH * 8);
    dim3 block(64, 4);
    up_kernel<<<grid, block>>>(out);
}